// round 15
// baseline (speedup 1.0000x reference)
#include <cuda_runtime.h>
#include <cuda_bf16.h>

// Problem constants (from reference): P=8, N=16, WS=32, H=W=512.
#define PP     8
#define NSLOT  16
#define WSZ    32
#define PITCH2 34            // window row pitch in float2 units
#define HDIM   512
#define WDIM   512
#define MAXM   625           // (32-8+1)^2
#define KPL    20            // elems per lane in selection warp (32*20=640>=625)
#define SPECX  248           // speculative ref coords (validated at runtime)
#define SPECY  248

#define FINF  __int_as_float(0x7f800000)
#define UINF  0x7f800000u

typedef unsigned long long u64;

__device__ __forceinline__ u64 pack2(float lo, float hi) {
    u64 r;
    asm("mov.b64 %0, {%1, %2};" : "=l"(r) : "f"(lo), "f"(hi));
    return r;
}
__device__ __forceinline__ float2 unpack2(u64 v) {
    float2 f;
    asm("mov.b64 {%0, %1}, %2;" : "=f"(f.x), "=f"(f.y) : "l"(v));
    return f;
}
// Packed fp32 add, round-to-nearest: bit-identical to the two scalar adds.
__device__ __forceinline__ u64 add2(u64 a, u64 b) {
    u64 r;
    asm("add.rn.f32x2 %0, %1, %2;" : "=l"(r) : "l"(a), "l"(b));
    return r;
}

// NPAT horizontally-adjacent patches sharing row loads. Accumulation order
// per patch identical to reference: i asc, j asc, re then im, one chain.
// Distances stored UNSCALED: a uniform exact power-of-2 scale preserves
// every strict comparison, and dists are only ever compared.
template<int NPAT>
__device__ __forceinline__ void dist_group(
    int px, int py0, int Pw,
    const u64 (*wp)[PITCH2], const u64 (*nref)[PP], float* dists)
{
    float s[NPAT];
    #pragma unroll
    for (int p = 0; p < NPAT; p++) s[p] = 0.0f;
    #pragma unroll
    for (int i = 0; i < PP; i++) {
        u64 nr[PP];
        #pragma unroll
        for (int j = 0; j < PP; j += 2) {
            const ulonglong2 q = *(const ulonglong2*)&nref[i][j];
            nr[j] = q.x; nr[j + 1] = q.y;
        }
        u64 w[NPAT + 7];
        #pragma unroll
        for (int c = 0; c < NPAT + 7; c++) w[c] = wp[px + i][py0 + c];
        #pragma unroll
        for (int p = 0; p < NPAT; p++) {
            float ss = s[p];
            #pragma unroll
            for (int j = 0; j < PP; j++) {
                const float2 d = unpack2(add2(w[p + j], nr[j]));
                ss = fmaf(d.x, d.x, ss);
                ss = fmaf(d.y, d.y, ss);
            }
            s[p] = ss;
        }
    }
    #pragma unroll
    for (int p = 0; p < NPAT; p++)
        dists[px * Pw + py0 + p] = s[p];
}

__global__ __launch_bounds__(256, 1)
void patches_kernel(const float* __restrict__ g_re,
                    const float* __restrict__ g_im,
                    const int*   __restrict__ p_refx,
                    const int*   __restrict__ p_refy,
                    float*       __restrict__ out)
{
    __shared__ u64   wp[WSZ][PITCH2];      // interleaved (re, im) window
    __shared__ u64   nref[PP][PP];         // NEGATED ref patch, interleaved
    __shared__ float dists[MAXM];
    __shared__ int   sel[NSLOT];

    const int bc   = blockIdx.x;
    const int tid  = threadIdx.x;
    const int lane = tid & 31;

    // Issue the (tiny) ref coordinate loads...
    const int ref_x = __ldg(p_refx);
    const int ref_y = __ldg(p_refy);

    const size_t base = (size_t)bc * HDIM * WDIM;

    // ...and CONCURRENTLY stage the window + ref patch speculatively for
    // ref=(SPECX,SPECY): constant, always-in-bounds addresses, so both GMEM
    // round-trips overlap instead of chaining.
    {
        const int swx0 = SPECX - WSZ / 2;          // 232
        const int swy0 = SPECY - WSZ / 2;          // 232, %4==0 -> float4 ok
        const int r  = tid >> 3;
        const int c4 = (tid & 7) << 2;
        const size_t gidx = base + (size_t)(swx0 + r) * WDIM + (swy0 + c4);
        const float4 re = *(const float4*)&g_re[gidx];
        const float4 im = *(const float4*)&g_im[gidx];
        wp[r][c4 + 0] = pack2(re.x, im.x);
        wp[r][c4 + 1] = pack2(re.y, im.y);
        wp[r][c4 + 2] = pack2(re.z, im.z);
        wp[r][c4 + 3] = pack2(re.w, im.w);
        if (tid < PP * PP) {
            const int i = tid >> 3, j = tid & 7;
            const size_t ridx = base + (size_t)(SPECX + i) * WDIM + (SPECY + j);
            nref[i][j] = pack2(-g_re[ridx], -g_im[ridx]);
        }
    }

    // Actual window geometry.
    int wx0 = ref_x - WSZ / 2; if (wx0 < 0) wx0 = 0;
    int wx1 = ref_x + WSZ / 2; if (wx1 > HDIM) wx1 = HDIM;
    int wy0 = ref_y - WSZ / 2; if (wy0 < 0) wy0 = 0;
    int wy1 = ref_y + WSZ / 2; if (wy1 > WDIM) wy1 = WDIM;
    const int Wh = wx1 - wx0;
    const int Ww = wy1 - wy0;
    const int Ph = Wh - PP + 1;
    const int Pw = Ww - PP + 1;
    const int M  = Ph * Pw;

    __syncthreads();

    if (ref_x != SPECX || ref_y != SPECY) {
        // Misprediction: reload generically (scalar, any alignment).
        for (int t = tid; t < Wh * Ww; t += 256) {
            const int r = t / Ww;
            const int c = t - r * Ww;
            const size_t gidx = base + (size_t)(wx0 + r) * WDIM + (wy0 + c);
            wp[r][c] = pack2(g_re[gidx], g_im[gidx]);
        }
        if (tid < PP * PP) {
            const int i = tid >> 3, j = tid & 7;
            const size_t gidx = base + (size_t)(ref_x + i) * WDIM + (ref_y + j);
            nref[i][j] = pack2(-g_re[gidx], -g_im[gidx]);
        }
        __syncthreads();
    }

    // ---- Distances ----
    if (Ph == (WSZ - PP + 1) && Pw == (WSZ - PP + 1)) {
        // Fast path, 8 warps, warp-uniform group widths:
        //   warps 0-3 (t<125):      3-col groups, cols 0..14
        //   warps 4-7 (128<=t<253): 2-col groups, cols 15..24
        if (tid < 125) {
            const int px = tid / 5;
            const int q  = tid - px * 5;
            dist_group<3>(px, 3 * q, Pw, wp, nref, dists);
        } else if (tid >= 128 && tid < 253) {
            const int u  = tid - 128;
            const int px = u / 5;
            const int q  = u - px * 5;
            dist_group<2>(px, 15 + 2 * q, Pw, wp, nref, dists);
        }
    } else {
        // Generic fallback (any window shape).
        for (int m = tid; m < M; m += 256) {
            const int px = m / Pw;
            const int py = m - px * Pw;
            float s = 0.0f;
            #pragma unroll
            for (int i = 0; i < PP; i++) {
                #pragma unroll
                for (int j = 0; j < PP; j++) {
                    const float2 d = unpack2(add2(wp[px + i][py + j], nref[i][j]));
                    s = fmaf(d.x, d.x, s);
                    s = fmaf(d.y, d.y, s);
                }
            }
            dists[m] = s;
        }
    }
    __syncthreads();

    // ---- Selection: patience-sort rounds in warp 0 (exact replay of
    //      reference slot semantics). Pile-j members = strict prefix-minima
    //      of the remaining subsequence; slot j = LAST member = max-index
    //      member (redux.max). The cross-lane exclusive prefix-min uses a
    //      two-level scan: width-8 segmented shfl scan (3 steps) in parallel
    //      with per-group redux.min + broadcasts (dists >= 0 => uint-min
    //      == float-min, +INF = 0x7f800000 orders correctly).
    if (tid < 32) {
        const int      grp   = lane >> 3;
        const unsigned gmask = 0xFFu << (grp << 3);
        float v[KPL];
        #pragma unroll
        for (int k = 0; k < KPL; k++) {
            const int m = lane * KPL + k;
            v[k] = (m < M) ? dists[m] : FINF;
        }
        for (int j = 0; j < NSLOT - 1; j++) {
            // Per-lane balanced tree-min (5 levels).
            float t[10];
            #pragma unroll
            for (int k = 0; k < 10; k++) t[k] = fminf(v[k], v[k + 10]);
            float u0 = fminf(t[0], t[5]);
            float u1 = fminf(t[1], t[6]);
            float u2 = fminf(t[2], t[7]);
            float u3 = fminf(t[3], t[8]);
            float u4 = fminf(t[4], t[9]);
            const float tm =
                fminf(fminf(fminf(u0, u1), fminf(u2, u3)), u4);

            // Path A (independent of path B): per-group min via redux,
            // then cross-group prefix from 3 broadcasts.
            const float gr = __uint_as_float(
                __reduce_min_sync(gmask, __float_as_uint(tm)));
            const float r0 = __shfl_sync(0xffffffffu, gr, 0);
            const float r1 = __shfl_sync(0xffffffffu, gr, 8);
            const float r2 = __shfl_sync(0xffffffffu, gr, 16);
            const float pg = (grp == 0) ? FINF
                           : (grp == 1) ? r0
                           : (grp == 2) ? fminf(r0, r1)
                                        : fminf(fminf(r0, r1), r2);

            // Path B: in-group (width-8) inclusive scan, 3 steps.
            float inc = tm;
            #pragma unroll
            for (int off = 1; off < 8; off <<= 1) {
                const float o = __shfl_up_sync(0xffffffffu, inc, off, 8);
                if ((lane & 7) >= off) inc = fminf(inc, o);
            }
            float excl = __shfl_up_sync(0xffffffffu, inc, 1, 8);
            if ((lane & 7) == 0) excl = FINF;

            const float bmin = fminf(excl, pg);

            // Per-lane serial exclusive prefix-min (overlaps the shfls).
            float pmk[KPL];
            float rm = FINF;
            #pragma unroll
            for (int k = 0; k < KPL; k++) { pmk[k] = rm; rm = fminf(rm, v[k]); }

            // Strict membership + removal; track lane's last member index.
            int last = -1;
            #pragma unroll
            for (int k = 0; k < KPL; k++) {
                const float lim = fminf(bmin, pmk[k]);
                if (v[k] < lim) { last = lane * KPL + k; v[k] = FINF; }
            }
            // Winner = max-index member (off the round-to-round chain).
            const int w = __reduce_max_sync(0xffffffffu, last);
            if (lane == 0) sel[j] = w;
        }
        // Final round shortcut: last pile's winner = FIRST occurrence of
        // min(remaining) — no scan / no removal needed.
        {
            float t[10];
            #pragma unroll
            for (int k = 0; k < 10; k++) t[k] = fminf(v[k], v[k + 10]);
            float u0 = fminf(t[0], t[5]);
            float u1 = fminf(t[1], t[6]);
            float u2 = fminf(t[2], t[7]);
            float u3 = fminf(t[3], t[8]);
            float u4 = fminf(t[4], t[9]);
            const float tm =
                fminf(fminf(fminf(u0, u1), fminf(u2, u3)), u4);
            const unsigned gmin =
                __reduce_min_sync(0xffffffffu, __float_as_uint(tm));
            int cand = 0x7fffffff;
            #pragma unroll
            for (int k = 0; k < KPL; k++)
                if (cand == 0x7fffffff && __float_as_uint(v[k]) == gmin)
                    cand = lane * KPL + k;
            const int w = __reduce_min_sync(0xffffffffu, (unsigned)cand);
            if (lane == 0)
                sel[NSLOT - 1] = (gmin >= UINF) ? -1 : w;
        }
    }
    __syncthreads();

    // ---- Gather winning patches: 1024 float2 stores per CTA.
    // out layout: [bc][slot][k=i*8+j][comp], comp fastest -> one float2 each.
    for (int t2 = tid; t2 < NSLOT * PP * PP; t2 += 256) {
        const int s = t2 >> 6;
        const int k = t2 & 63;
        const int m = sel[s];
        float2 v = make_float2(0.0f, 0.0f);   // unfilled slot -> zeros
        if (m >= 0) {
            const int px = m / Pw;
            const int py = m - px * Pw;
            v = unpack2(wp[px + (k >> 3)][py + (k & 7)]);
        }
        *(float2*)&out[(size_t)bc * (NSLOT * PP * PP * 2) + 2 * t2] = v;
    }
}

extern "C" void kernel_launch(void* const* d_in, const int* in_sizes, int n_in,
                              void* d_out, int out_size)
{
    const float* g_re = (const float*)d_in[0];
    const float* g_im = (const float*)d_in[1];
    const int*   refx = (const int*)d_in[2];
    const int*   refy = (const int*)d_in[3];
    float*       out  = (float*)d_out;

    const int BC = in_sizes[0] / (HDIM * WDIM);   // 96
    patches_kernel<<<BC, 256>>>(g_re, g_im, refx, refy, out);
}

// round 16
// speedup vs baseline: 1.3780x; 1.3780x over previous
#include <cuda_runtime.h>
#include <cuda_bf16.h>

// Problem constants (from reference): P=8, N=16, WS=32, H=W=512.
#define PP     8
#define NSLOT  16
#define WSZ    32
#define PITCH2 34            // window row pitch in float2 units
#define HDIM   512
#define WDIM   512
#define MAXM   625           // (32-8+1)^2
#define KPL    20            // elems per lane in selection warp (32*20=640>=625)
#define SPECX  248           // speculative ref coords (validated at runtime)
#define SPECY  248

#define FINF  __int_as_float(0x7f800000)
#define UINF  0x7f800000u

typedef unsigned long long u64;

__device__ __forceinline__ u64 pack2(float lo, float hi) {
    u64 r;
    asm("mov.b64 %0, {%1, %2};" : "=l"(r) : "f"(lo), "f"(hi));
    return r;
}
__device__ __forceinline__ float2 unpack2(u64 v) {
    float2 f;
    asm("mov.b64 {%0, %1}, %2;" : "=f"(f.x), "=f"(f.y) : "l"(v));
    return f;
}
// Packed fp32 add, round-to-nearest: bit-identical to the two scalar adds.
__device__ __forceinline__ u64 add2(u64 a, u64 b) {
    u64 r;
    asm("add.rn.f32x2 %0, %1, %2;" : "=l"(r) : "l"(a), "l"(b));
    return r;
}

// NPAT horizontally-adjacent patches sharing row loads. Accumulation order
// per patch identical to reference: i asc, j asc, re then im, one chain.
// Distances stored UNSCALED: a uniform exact power-of-2 scale preserves
// every strict comparison, and dists are only ever compared.
template<int NPAT>
__device__ __forceinline__ void dist_group(
    int px, int py0, int Pw,
    const u64 (*wp)[PITCH2], const u64 (*nref)[PP], float* dists)
{
    float s[NPAT];
    #pragma unroll
    for (int p = 0; p < NPAT; p++) s[p] = 0.0f;
    #pragma unroll
    for (int i = 0; i < PP; i++) {
        u64 nr[PP];
        #pragma unroll
        for (int j = 0; j < PP; j += 2) {
            const ulonglong2 q = *(const ulonglong2*)&nref[i][j];
            nr[j] = q.x; nr[j + 1] = q.y;
        }
        u64 w[NPAT + 7];
        #pragma unroll
        for (int c = 0; c < NPAT + 7; c++) w[c] = wp[px + i][py0 + c];
        #pragma unroll
        for (int p = 0; p < NPAT; p++) {
            float ss = s[p];
            #pragma unroll
            for (int j = 0; j < PP; j++) {
                const float2 d = unpack2(add2(w[p + j], nr[j]));
                ss = fmaf(d.x, d.x, ss);
                ss = fmaf(d.y, d.y, ss);
            }
            s[p] = ss;
        }
    }
    #pragma unroll
    for (int p = 0; p < NPAT; p++)
        dists[px * Pw + py0 + p] = s[p];
}

__global__ __launch_bounds__(256, 1)
void patches_kernel(const float* __restrict__ g_re,
                    const float* __restrict__ g_im,
                    const int*   __restrict__ p_refx,
                    const int*   __restrict__ p_refy,
                    float*       __restrict__ out)
{
    __shared__ u64   wp[WSZ][PITCH2];      // interleaved (re, im) window
    __shared__ u64   nref[PP][PP];         // NEGATED ref patch, interleaved
    __shared__ float dists[MAXM];
    __shared__ int   sel[NSLOT];

    const int bc   = blockIdx.x;
    const int tid  = threadIdx.x;
    const int lane = tid & 31;

    // Issue the (tiny) ref coordinate loads...
    const int ref_x = __ldg(p_refx);
    const int ref_y = __ldg(p_refy);

    const size_t base = (size_t)bc * HDIM * WDIM;

    // ...and CONCURRENTLY stage the window + ref patch speculatively for
    // ref=(SPECX,SPECY): constant, always-in-bounds addresses, so both GMEM
    // round-trips overlap instead of chaining.
    {
        const int swx0 = SPECX - WSZ / 2;          // 232
        const int swy0 = SPECY - WSZ / 2;          // 232, %4==0 -> float4 ok
        const int r  = tid >> 3;
        const int c4 = (tid & 7) << 2;
        const size_t gidx = base + (size_t)(swx0 + r) * WDIM + (swy0 + c4);
        const float4 re = *(const float4*)&g_re[gidx];
        const float4 im = *(const float4*)&g_im[gidx];
        wp[r][c4 + 0] = pack2(re.x, im.x);
        wp[r][c4 + 1] = pack2(re.y, im.y);
        wp[r][c4 + 2] = pack2(re.z, im.z);
        wp[r][c4 + 3] = pack2(re.w, im.w);
        if (tid < PP * PP) {
            const int i = tid >> 3, j = tid & 7;
            const size_t ridx = base + (size_t)(SPECX + i) * WDIM + (SPECY + j);
            nref[i][j] = pack2(-g_re[ridx], -g_im[ridx]);
        }
    }

    // Actual window geometry.
    int wx0 = ref_x - WSZ / 2; if (wx0 < 0) wx0 = 0;
    int wx1 = ref_x + WSZ / 2; if (wx1 > HDIM) wx1 = HDIM;
    int wy0 = ref_y - WSZ / 2; if (wy0 < 0) wy0 = 0;
    int wy1 = ref_y + WSZ / 2; if (wy1 > WDIM) wy1 = WDIM;
    const int Wh = wx1 - wx0;
    const int Ww = wy1 - wy0;
    const int Ph = Wh - PP + 1;
    const int Pw = Ww - PP + 1;
    const int M  = Ph * Pw;

    __syncthreads();

    if (ref_x != SPECX || ref_y != SPECY) {
        // Misprediction: reload generically (scalar, any alignment).
        for (int t = tid; t < Wh * Ww; t += 256) {
            const int r = t / Ww;
            const int c = t - r * Ww;
            const size_t gidx = base + (size_t)(wx0 + r) * WDIM + (wy0 + c);
            wp[r][c] = pack2(g_re[gidx], g_im[gidx]);
        }
        if (tid < PP * PP) {
            const int i = tid >> 3, j = tid & 7;
            const size_t gidx = base + (size_t)(ref_x + i) * WDIM + (ref_y + j);
            nref[i][j] = pack2(-g_re[gidx], -g_im[gidx]);
        }
        __syncthreads();
    }

    // ---- Distances ----
    if (Ph == (WSZ - PP + 1) && Pw == (WSZ - PP + 1)) {
        // Fast path, 8 warps, warp-uniform group widths:
        //   warps 0-3 (t<125):      3-col groups, cols 0..14
        //   warps 4-7 (128<=t<253): 2-col groups, cols 15..24
        if (tid < 125) {
            const int px = tid / 5;
            const int q  = tid - px * 5;
            dist_group<3>(px, 3 * q, Pw, wp, nref, dists);
        } else if (tid >= 128 && tid < 253) {
            const int u  = tid - 128;
            const int px = u / 5;
            const int q  = u - px * 5;
            dist_group<2>(px, 15 + 2 * q, Pw, wp, nref, dists);
        }
    } else {
        // Generic fallback (any window shape).
        for (int m = tid; m < M; m += 256) {
            const int px = m / Pw;
            const int py = m - px * Pw;
            float s = 0.0f;
            #pragma unroll
            for (int i = 0; i < PP; i++) {
                #pragma unroll
                for (int j = 0; j < PP; j++) {
                    const float2 d = unpack2(add2(wp[px + i][py + j], nref[i][j]));
                    s = fmaf(d.x, d.x, s);
                    s = fmaf(d.y, d.y, s);
                }
            }
            dists[m] = s;
        }
    }
    __syncthreads();

    // ---- Selection: patience-sort rounds in warp 0 (exact replay of
    //      reference slot semantics). Pile-j members = strict prefix-minima
    //      of the remaining subsequence; members strictly decrease in value,
    //      so slot j's final content = LAST member = max-index member,
    //      extracted with a single full-mask redux.max (off-chain).
    if (tid < 32) {
        float v[KPL];
        #pragma unroll
        for (int k = 0; k < KPL; k++) {
            const int m = lane * KPL + k;
            v[k] = (m < M) ? dists[m] : FINF;
        }
        for (int j = 0; j < NSLOT - 1; j++) {
            // Per-lane balanced tree-min (5 levels).
            float t[10];
            #pragma unroll
            for (int k = 0; k < 10; k++) t[k] = fminf(v[k], v[k + 10]);
            float u0 = fminf(t[0], t[5]);
            float u1 = fminf(t[1], t[6]);
            float u2 = fminf(t[2], t[7]);
            float u3 = fminf(t[3], t[8]);
            float u4 = fminf(t[4], t[9]);
            const float tm =
                fminf(fminf(fminf(u0, u1), fminf(u2, u3)), u4);

            // Cross-lane exclusive prefix-min (critical chain, 5-shfl
            // Kogge-Stone — structural floor for a 32-lane prefix).
            float inc = tm;
            #pragma unroll
            for (int off = 1; off < 32; off <<= 1) {
                const float o = __shfl_up_sync(0xffffffffu, inc, off);
                if (lane >= off) inc = fminf(inc, o);
            }
            float bmin = __shfl_up_sync(0xffffffffu, inc, 1);
            if (lane == 0) bmin = FINF;

            // Per-lane serial exclusive prefix-min (overlaps the shfls).
            float pmk[KPL];
            float rm = FINF;
            #pragma unroll
            for (int k = 0; k < KPL; k++) { pmk[k] = rm; rm = fminf(rm, v[k]); }

            // Strict membership + removal; track lane's last member index.
            int last = -1;
            #pragma unroll
            for (int k = 0; k < KPL; k++) {
                const float lim = fminf(bmin, pmk[k]);
                if (v[k] < lim) { last = lane * KPL + k; v[k] = FINF; }
            }
            // Winner = max-index member (off the round-to-round chain).
            const int w = __reduce_max_sync(0xffffffffu, last);
            if (lane == 0) sel[j] = w;
        }
        // Final round shortcut: last pile's winner = FIRST occurrence of
        // min(remaining) — no scan / no removal needed.
        {
            float t[10];
            #pragma unroll
            for (int k = 0; k < 10; k++) t[k] = fminf(v[k], v[k + 10]);
            float u0 = fminf(t[0], t[5]);
            float u1 = fminf(t[1], t[6]);
            float u2 = fminf(t[2], t[7]);
            float u3 = fminf(t[3], t[8]);
            float u4 = fminf(t[4], t[9]);
            const float tm =
                fminf(fminf(fminf(u0, u1), fminf(u2, u3)), u4);
            const unsigned gmin =
                __reduce_min_sync(0xffffffffu, __float_as_uint(tm));
            int cand = 0x7fffffff;
            #pragma unroll
            for (int k = 0; k < KPL; k++)
                if (cand == 0x7fffffff && __float_as_uint(v[k]) == gmin)
                    cand = lane * KPL + k;
            const int w = __reduce_min_sync(0xffffffffu, (unsigned)cand);
            if (lane == 0)
                sel[NSLOT - 1] = (gmin >= UINF) ? -1 : w;
        }
    }
    __syncthreads();

    // ---- Gather winning patches: 512 STG.128 per CTA (paired float2s).
    // out layout: [bc][slot][k=i*8+j][comp], comp fastest. Items t2 and
    // t2+1 are contiguous 16B in out -> one float4 store.
    for (int t4 = tid; t4 < NSLOT * PP * PP / 2; t4 += 256) {
        const int s  = t4 >> 5;          // 32 float4 per slot
        const int k0 = (t4 & 31) << 1;   // even k
        const int m  = sel[s];
        float4 v = make_float4(0.0f, 0.0f, 0.0f, 0.0f);
        if (m >= 0) {
            const int px = m / Pw;
            const int py = m - px * Pw;
            const int i  = k0 >> 3;
            const int j0 = k0 & 7;       // j0 even, j0+1 same row (<8)
            const float2 a = unpack2(wp[px + i][py + j0]);
            const float2 b = unpack2(wp[px + i][py + j0 + 1]);
            v = make_float4(a.x, a.y, b.x, b.y);
        }
        *(float4*)&out[(size_t)bc * (NSLOT * PP * PP * 2) + 4 * t4] = v;
    }
}

extern "C" void kernel_launch(void* const* d_in, const int* in_sizes, int n_in,
                              void* d_out, int out_size)
{
    const float* g_re = (const float*)d_in[0];
    const float* g_im = (const float*)d_in[1];
    const int*   refx = (const int*)d_in[2];
    const int*   refy = (const int*)d_in[3];
    float*       out  = (float*)d_out;

    const int BC = in_sizes[0] / (HDIM * WDIM);   // 96
    patches_kernel<<<BC, 256>>>(g_re, g_im, refx, refy, out);
}